// round 14
// baseline (speedup 1.0000x reference)
#include <cuda_runtime.h>
#include <cuda_fp16.h>
#include <cstdint>
#include <math.h>

#define HIDDEN 1024
#define INNER  2048
#define STATE  16
#define BATCH  4
#define SEQ    2048
#define TOK    (BATCH*SEQ)   // 8192
#define NCAT   2304          // 2048 dt | 16 B | 16 C | 224 pad (9 tiles of 256)

// ---------------- scratch (static device globals) ---------------------------
__device__ __half g_xnh[TOK*HIDDEN];             // ln output (f16, GEMM1 A)
__device__ float g_xz[TOK*2*INNER];              // GEMM1 out [xb_raw | z] fp32
__device__ float g_xb[TOK*INNER];                // conv+silu fp32 (scan)
__device__ __half g_xbh[TOK*INNER];              // conv+silu f16 (GEMM2 A)
__device__ float g_dtbc[TOK*NCAT];               // [softplus(dt) | B | C | pad]
__device__ __half g_yh[TOK*INNER];               // gated SSM output (f16, GEMM3 A)
__device__ __half g_WinTh [2*INNER*HIDDEN];
__device__ __half g_WcatTh[NCAT*INNER];
__device__ __half g_WoutTh[HIDDEN*INNER];

// ============================== helpers =====================================
__device__ __forceinline__ void cp16(uint32_t s, const void* g) {
    asm volatile("cp.async.cg.shared.global [%0], [%1], 16;" :: "r"(s), "l"(g));
}
__device__ __forceinline__ void cp_commit() {
    asm volatile("cp.async.commit_group;" ::: "memory");
}
template<int N> __device__ __forceinline__ void cp_wait() {
    asm volatile("cp.async.wait_group %0;" :: "n"(N) : "memory");
}
// f16 mma, fresh accumulator (c = 0)
__device__ __forceinline__ void mma_f16_init(uint32_t& d0, uint32_t& d1,
                                             const uint32_t* a, const uint32_t* b) {
    asm volatile("mma.sync.aligned.m16n8k16.row.col.f16.f16.f16.f16 "
                 "{%0,%1},{%2,%3,%4,%5},{%6,%7},{%8,%9};"
                 : "=r"(d0), "=r"(d1)
                 : "r"(a[0]), "r"(a[1]), "r"(a[2]), "r"(a[3]),
                   "r"(b[0]), "r"(b[1]), "r"(0u), "r"(0u));
}
// f16 mma, accumulate in place
__device__ __forceinline__ void mma_f16_acc(uint32_t& d0, uint32_t& d1,
                                            const uint32_t* a, const uint32_t* b) {
    asm volatile("mma.sync.aligned.m16n8k16.row.col.f16.f16.f16.f16 "
                 "{%0,%1},{%2,%3,%4,%5},{%6,%7},{%0,%1};"
                 : "+r"(d0), "+r"(d1)
                 : "r"(a[0]), "r"(a[1]), "r"(a[2]), "r"(a[3]),
                   "r"(b[0]), "r"(b[1]));
}
__device__ __forceinline__ void ldmx4(uint32_t* r, uint32_t addr) {
    asm volatile("ldmatrix.sync.aligned.m8n8.x4.shared.b16 {%0,%1,%2,%3}, [%4];"
                 : "=r"(r[0]), "=r"(r[1]), "=r"(r[2]), "=r"(r[3]) : "r"(addr));
}
__device__ __forceinline__ float softplus_f(float v) {
    return fmaxf(v, 0.f) + __logf(1.f + __expf(-fabsf(v)));
}

// ====================== f16 mma.sync GEMM (f16 acc, f32 promote) ============
// C[M,N] = A[M,K] @ Bt[N,K]^T, f16 in, f16 chunk-acc (K=32) promoted to f32.
// BM=128, BN=256, BK=32, 256 threads (2x4 warps, 64x64 warp tiles),
// 4-stage cp.async pipeline. Rows padded to 80 B -> LDSM conflict-free.
// EPI: 0 plain, 1 mixed softplus(dt)|raw(bc), 2 +residual
#define PADH_B 80
#define AH_STAGE_B (128*PADH_B)               // 10240
#define BH_STAGE_B (256*PADH_B)               // 20480
#define GSMEMH (4*(AH_STAGE_B + BH_STAGE_B))  // 122880

template<int EPI>
__global__ __launch_bounds__(256) void gemm_f16k(
    const __half* __restrict__ A, const __half* __restrict__ Bt,
    float* __restrict__ C, int M, int N, int K,
    const float* __restrict__ bias, const float* __restrict__ resid)
{
    extern __shared__ char smemc[];
    char* Abase = smemc;
    char* Bbase = smemc + 4*AH_STAGE_B;

    int tid = threadIdx.x, lane = tid & 31, wid = tid >> 5;
    int wm = wid >> 2, wn = wid & 3;
    int m0 = blockIdx.y * 128, n0 = blockIdx.x * 256;

    uint32_t uA = (uint32_t)__cvta_generic_to_shared(Abase);
    uint32_t uB = (uint32_t)__cvta_generic_to_shared(Bbase);

    const __half* Agm = A  + (size_t)m0 * K;
    const __half* Bgm = Bt + (size_t)n0 * K;

    int ns = K >> 5;                          // BK = 32

    auto load_stage = [&](int s) {
        int buf = s & 3;
        const __half* Ak = Agm + s * 32;
        const __half* Bk = Bgm + s * 32;
        uint32_t ab = uA + buf * AH_STAGE_B;
        uint32_t bb = uB + buf * BH_STAGE_B;
        #pragma unroll
        for (int i = 0; i < 2; i++) {
            int e = tid + i * 256;
            int row = e >> 2, c4 = e & 3;
            cp16(ab + (uint32_t)(row*PADH_B + c4*16), Ak + (size_t)row * K + c4*8);
        }
        #pragma unroll
        for (int i = 0; i < 4; i++) {
            int e = tid + i * 256;
            int row = e >> 2, c4 = e & 3;
            cp16(bb + (uint32_t)(row*PADH_B + c4*16), Bk + (size_t)row * K + c4*8);
        }
        cp_commit();
    };

    load_stage(0); load_stage(1); load_stage(2);

    float acc[4][8][4] = {};

    // ldmatrix lane-offset maps (bytes)
    uint32_t aOff = (uint32_t)(((lane & 7) + ((lane >> 3) & 1) * 8) * PADH_B
                               + (lane >> 4) * 16);
    uint32_t bOff = (uint32_t)(((lane & 7) + (lane >> 4) * 8) * PADH_B
                               + ((lane >> 3) & 1) * 16);
    uint32_t aWarp = uA + (uint32_t)(wm*64*PADH_B) + aOff;
    uint32_t bWarp = uB + (uint32_t)(wn*64*PADH_B) + bOff;

    for (int s = 0; s < ns; s++) {
        cp_wait<2>();
        __syncthreads();
        if (s + 3 < ns) load_stage(s + 3);

        int buf = s & 3;
        uint32_t aStage = aWarp + buf * AH_STAGE_B;
        uint32_t bStage = bWarp + buf * BH_STAGE_B;

        // load fragments for both k16 slices of this stage
        uint32_t af0[4][4], af1[4][4], bf0[4][4], bf1[4][4];
        #pragma unroll
        for (int am = 0; am < 4; am++) {
            ldmx4(af0[am], aStage + (uint32_t)(am*16*PADH_B));
            ldmx4(af1[am], aStage + (uint32_t)(am*16*PADH_B + 32));
        }
        #pragma unroll
        for (int bp = 0; bp < 4; bp++) {
            ldmx4(bf0[bp], bStage + (uint32_t)(bp*16*PADH_B));
            ldmx4(bf1[bp], bStage + (uint32_t)(bp*16*PADH_B + 32));
        }

        // per tile: two f16 MMAs (K=32 chunk) then promote to f32
        #pragma unroll
        for (int am = 0; am < 4; am++) {
            #pragma unroll
            for (int bn = 0; bn < 8; bn++) {
                uint32_t h0, h1;
                mma_f16_init(h0, h1, af0[am], &bf0[bn >> 1][(bn & 1) * 2]);
                mma_f16_acc (h0, h1, af1[am], &bf1[bn >> 1][(bn & 1) * 2]);
                float2 flo = __half22float2(*reinterpret_cast<__half2*>(&h0));
                float2 fhi = __half22float2(*reinterpret_cast<__half2*>(&h1));
                acc[am][bn][0] += flo.x;
                acc[am][bn][1] += flo.y;
                acc[am][bn][2] += fhi.x;
                acc[am][bn][3] += fhi.y;
            }
        }
    }

    int r = lane >> 2, c = lane & 3;
    #pragma unroll
    for (int am = 0; am < 4; am++) {
        int row0 = m0 + wm*64 + am*16 + r;
        #pragma unroll
        for (int bn = 0; bn < 8; bn++) {
            int col = n0 + wn*64 + bn*8 + 2*c;
            #pragma unroll
            for (int h = 0; h < 2; h++) {
                int row = row0 + h*8;
                float v0 = acc[am][bn][h*2 + 0];
                float v1 = acc[am][bn][h*2 + 1];
                if (EPI == 1) {
                    if (col < 2048) {
                        v0 = softplus_f(v0 + bias[col]);
                        v1 = softplus_f(v1 + bias[col + 1]);
                    }
                } else if (EPI == 2) {
                    const float* rp = resid + (size_t)row * N + col;
                    v0 += rp[0]; v1 += rp[1];
                }
                *(float2*)(C + (size_t)row * N + col) = make_float2(v0, v1);
            }
        }
    }
}

// ------------------------------- weight prep --------------------------------
__global__ __launch_bounds__(256) void tr_f16(
    const float* __restrict__ in, __half* __restrict__ out, int K, int N)
{   // in [K,N] fp32 -> out [N,K] f16
    __shared__ float tile[32][33];
    int tx = threadIdx.x, ty = threadIdx.y;
    int x = blockIdx.x * 32 + tx;
    int y = blockIdx.y * 32 + ty;
    #pragma unroll
    for (int j = 0; j < 32; j += 8)
        tile[ty + j][tx] = in[(size_t)(y + j) * N + x];
    __syncthreads();
    int x2 = blockIdx.y * 32 + tx;
    int y2 = blockIdx.x * 32 + ty;
    #pragma unroll
    for (int j = 0; j < 32; j += 8)
        out[(size_t)(y2 + j) * K + x2] = __float2half_rn(tile[tx][ty + j]);
}

__global__ __launch_bounds__(256) void wbc_kernel(
    const float* __restrict__ WB, const float* __restrict__ WC)
{   // rows 2048..2303 of g_WcatTh: W_B^T, W_C^T, zeros
    int idx = blockIdx.x * 256 + threadIdx.x;     // 256*2048
    int j = idx >> 11, k = idx & 2047;
    float v = (j < 16) ? WB[(size_t)k*STATE + j]
            : (j < 32) ? WC[(size_t)k*STATE + (j - 16)]
            : 0.f;
    g_WcatTh[(size_t)(2048 + j) * INNER + k] = __float2half_rn(v);
}

// ---------------------------------------------------------------- LayerNorm
__global__ __launch_bounds__(256) void ln_kernel(
    const float* __restrict__ x, const float* __restrict__ g,
    const float* __restrict__ bt)
{
    int r = blockIdx.x, t = threadIdx.x;
    float4 v = *(const float4*)(x + (size_t)r*HIDDEN + t*4);
    float s  = v.x + v.y + v.z + v.w;
    float s2 = v.x*v.x + v.y*v.y + v.z*v.z + v.w*v.w;
    #pragma unroll
    for (int off = 16; off > 0; off >>= 1) {
        s  += __shfl_xor_sync(0xffffffffu, s,  off);
        s2 += __shfl_xor_sync(0xffffffffu, s2, off);
    }
    __shared__ float a1[8], a2[8];
    if ((t & 31) == 0) { a1[t >> 5] = s; a2[t >> 5] = s2; }
    __syncthreads();
    float ts = 0.f, ts2 = 0.f;
    #pragma unroll
    for (int i = 0; i < 8; i++) { ts += a1[i]; ts2 += a2[i]; }
    float mu   = ts * (1.f / HIDDEN);
    float var  = fmaf(ts2, 1.f / HIDDEN, -mu * mu);
    float rstd = rsqrtf(var + 1e-5f);
    float4 g4 = *(const float4*)(g  + t*4);
    float4 b4 = *(const float4*)(bt + t*4);
    float4 ov;
    ov.x = (v.x - mu) * rstd * g4.x + b4.x;
    ov.y = (v.y - mu) * rstd * g4.y + b4.y;
    ov.z = (v.z - mu) * rstd * g4.z + b4.z;
    ov.w = (v.w - mu) * rstd * g4.w + b4.w;
    union { __half2 h[2]; uint2 u; } pk;
    pk.h[0] = __floats2half2_rn(ov.x, ov.y);
    pk.h[1] = __floats2half2_rn(ov.z, ov.w);
    *(uint2*)(g_xnh + (size_t)r*HIDDEN + t*4) = pk.u;
}

// ----------------------------------------------- depthwise conv (k=3) + SiLU
__global__ __launch_bounds__(256) void conv_kernel(
    const float* __restrict__ cw, const float* __restrict__ cb)
{
    int idx = blockIdx.x * 256 + threadIdx.x;
    int d4 = idx & 511;
    int r  = idx >> 9;
    int l  = r & (SEQ - 1);
    const float* base = g_xz + (size_t)r*(2*INNER) + d4*4;
    float4 zero = make_float4(0.f, 0.f, 0.f, 0.f);
    float4 xm = (l > 0)       ? *(const float4*)(base - 2*INNER) : zero;
    float4 xc = *(const float4*)(base);
    float4 xp = (l < SEQ - 1) ? *(const float4*)(base + 2*INNER) : zero;
    const float4* cwp = (const float4*)(cw + d4*12);
    float4 t0 = cwp[0], t1 = cwp[1], t2 = cwp[2];
    float4 b4 = *(const float4*)(cb + d4*4);
    float o0 = t0.x*xm.x + t0.y*xc.x + t0.z*xp.x + b4.x;
    float o1 = t0.w*xm.y + t1.x*xc.y + t1.y*xp.y + b4.y;
    float o2 = t1.z*xm.z + t1.w*xc.z + t2.x*xp.z + b4.z;
    float o3 = t2.y*xm.w + t2.z*xc.w + t2.w*xp.w + b4.w;
    o0 *= __fdividef(1.f, 1.f + __expf(-o0));
    o1 *= __fdividef(1.f, 1.f + __expf(-o1));
    o2 *= __fdividef(1.f, 1.f + __expf(-o2));
    o3 *= __fdividef(1.f, 1.f + __expf(-o3));
    *(float4*)(g_xb + (size_t)r*INNER + d4*4) = make_float4(o0, o1, o2, o3);
    union { __half2 h[2]; uint2 u; } pk;
    pk.h[0] = __floats2half2_rn(o0, o1);
    pk.h[1] = __floats2half2_rn(o2, o3);
    *(uint2*)(g_xbh + (size_t)r*INNER + d4*4) = pk.u;
}

// ---------------------------- selective scan + gating -----------------------
__global__ __launch_bounds__(128) void scan_kernel(
    const float* __restrict__ A_log, const float* __restrict__ Dp)
{
    __shared__ float s_dt[2][16][16];
    __shared__ float s_x [2][16][16];
    __shared__ float s_z [2][16][16];
    __shared__ float s_bc[2][16][32];
    __shared__ float s_y [16][16];

    int tid = threadIdx.x;
    int b  = blockIdx.x >> 7;
    int d0 = (blockIdx.x & 127) * 16;
    int q  = tid & 7, dl = tid >> 3;
    int d  = d0 + dl;

    float a0 = -__expf(A_log[d*STATE + 2*q]);
    float a1 = -__expf(A_log[d*STATE + 2*q + 1]);
    float Dd = Dp[d];
    size_t tokbase = (size_t)b * SEQ;

    uint32_t u_dt = (uint32_t)__cvta_generic_to_shared(&s_dt[0][0][0]);
    uint32_t u_x  = (uint32_t)__cvta_generic_to_shared(&s_x [0][0][0]);
    uint32_t u_z  = (uint32_t)__cvta_generic_to_shared(&s_z [0][0][0]);
    uint32_t u_bc = (uint32_t)__cvta_generic_to_shared(&s_bc[0][0][0]);

    auto stage = [&](int s) {
        int l0 = s * 16, buf = s & 1;
        #pragma unroll
        for (int ii = tid; ii < 320; ii += 128) {
            if (ii < 192) {
                int arr = ii >> 6, e = ii & 63;
                int rowi = e >> 2, c4 = e & 3;
                size_t tok = tokbase + l0 + rowi;
                uint32_t doff = (uint32_t)((rowi*16 + c4*4) * 4) + buf*1024;
                if (arr == 0)
                    cp16(u_dt + doff, g_dtbc + tok*NCAT + d0 + c4*4);
                else if (arr == 1)
                    cp16(u_x + doff, g_xb + tok*INNER + d0 + c4*4);
                else
                    cp16(u_z + doff, g_xz + tok*(2*INNER) + INNER + d0 + c4*4);
            } else {
                int e = ii - 192;
                int rowi = e >> 3, c8 = e & 7;
                size_t tok = tokbase + l0 + rowi;
                cp16(u_bc + buf*2048 + (uint32_t)((rowi*32 + c8*4) * 4),
                     g_dtbc + tok*NCAT + 2048 + c8*4);
            }
        }
    };

    stage(0); cp_commit();

    float h0 = 0.f, h1 = 0.f;
    for (int s = 0; s < SEQ/16; s++) {
        if (s + 1 < SEQ/16) { stage(s + 1); cp_commit(); cp_wait<1>(); }
        else cp_wait<0>();
        __syncthreads();

        int buf = s & 1;
        #pragma unroll
        for (int i = 0; i < 16; i++) {
            float dtc = s_dt[buf][i][dl];
            float xc  = s_x [buf][i][dl];
            float2 Bv = *(const float2*)&s_bc[buf][i][2*q];
            float2 Cv = *(const float2*)&s_bc[buf][i][16 + 2*q];
            float e0 = __expf(dtc * a0);
            float e1 = __expf(dtc * a1);
            float dx = dtc * xc;
            h0 = fmaf(e0, h0, dx * Bv.x);
            h1 = fmaf(e1, h1, dx * Bv.y);
            float p = fmaf(h1, Cv.y, h0 * Cv.x);
            p += __shfl_xor_sync(0xffffffffu, p, 1);
            p += __shfl_xor_sync(0xffffffffu, p, 2);
            p += __shfl_xor_sync(0xffffffffu, p, 4);
            if (q == 0) {
                float zz  = s_z[buf][i][dl];
                float sil = zz * __fdividef(1.f, 1.f + __expf(-zz));
                s_y[i][dl] = fmaf(Dd, xc, p) * sil;
            }
        }
        __syncthreads();
        if (tid < 64) {
            int rowi = tid >> 2, c4 = tid & 3;
            float4 v = *(float4*)&s_y[rowi][c4*4];
            union { __half2 h[2]; uint2 u; } pk;
            pk.h[0] = __floats2half2_rn(v.x, v.y);
            pk.h[1] = __floats2half2_rn(v.z, v.w);
            *(uint2*)(g_yh + (tokbase + s*16 + rowi)*INNER + d0 + c4*4) = pk.u;
        }
    }
}

// ------------------------------------------------------------------- launch
extern "C" void kernel_launch(void* const* d_in, const int* in_sizes, int n_in,
                              void* d_out, int out_size)
{
    const float* x    = (const float*)d_in[0];
    const float* ns   = (const float*)d_in[1];
    const float* nb   = (const float*)d_in[2];
    const float* Win  = (const float*)d_in[3];
    const float* cw   = (const float*)d_in[4];
    const float* cb   = (const float*)d_in[5];
    const float* Wdt  = (const float*)d_in[6];
    const float* bdt  = (const float*)d_in[7];
    const float* Alog = (const float*)d_in[8];
    const float* Dp   = (const float*)d_in[9];
    const float* WB   = (const float*)d_in[10];
    const float* WC   = (const float*)d_in[11];
    const float* Wout = (const float*)d_in[12];
    float* out = (float*)d_out;

    void *p_xnh, *p_xz, *p_xbh, *p_dtbc, *p_yh, *p_winth, *p_wcatth, *p_woutth;
    cudaGetSymbolAddress(&p_xnh,  g_xnh);
    cudaGetSymbolAddress(&p_xz,   g_xz);
    cudaGetSymbolAddress(&p_xbh,  g_xbh);
    cudaGetSymbolAddress(&p_dtbc, g_dtbc);
    cudaGetSymbolAddress(&p_yh,   g_yh);
    cudaGetSymbolAddress(&p_winth,  g_WinTh);
    cudaGetSymbolAddress(&p_wcatth, g_WcatTh);
    cudaGetSymbolAddress(&p_woutth, g_WoutTh);
    __half* xnh   = (__half*)p_xnh;
    float*  xz    = (float*)p_xz;
    __half* xbh   = (__half*)p_xbh;
    float*  dtbc  = (float*)p_dtbc;
    __half* yh    = (__half*)p_yh;
    __half* WinTh  = (__half*)p_winth;
    __half* WcatTh = (__half*)p_wcatth;
    __half* WoutTh = (__half*)p_woutth;

    cudaFuncSetAttribute(gemm_f16k<0>, cudaFuncAttributeMaxDynamicSharedMemorySize, GSMEMH);
    cudaFuncSetAttribute(gemm_f16k<1>, cudaFuncAttributeMaxDynamicSharedMemorySize, GSMEMH);
    cudaFuncSetAttribute(gemm_f16k<2>, cudaFuncAttributeMaxDynamicSharedMemorySize, GSMEMH);

    // launch order: gemm_f16k<0> is the 4th launch (ncu target)
    // 1) Win -> WinTh (f16)
    tr_f16<<<dim3(2*INNER/32, HIDDEN/32), dim3(32,8)>>>(Win, WinTh, HIDDEN, 2*INNER);
    // 2) LayerNorm -> f16
    ln_kernel<<<TOK, 256>>>(x, ns, nb);
    // 3) WB/WC rows of WcatTh
    wbc_kernel<<<(256*2048)/256, 256>>>(WB, WC);
    // 4) xz = xn @ W_in   (f16 mma)  <-- profiled
    gemm_f16k<0><<<dim3(2*INNER/256, TOK/128), 256, GSMEMH>>>(
        xnh, WinTh, xz, TOK, 2*INNER, HIDDEN, nullptr, nullptr);
    // 5) Wdt -> WcatTh rows 0..2047
    tr_f16<<<dim3(INNER/32, INNER/32), dim3(32,8)>>>(Wdt, WcatTh, INNER, INNER);
    // 6) conv + SiLU (fp32 + f16 outputs)
    conv_kernel<<<(TOK*INNER/4)/256, 256>>>(cw, cb);
    // 7) [dt | B | C] = xb @ Wcat  (f16 mma, softplus on dt cols)
    gemm_f16k<1><<<dim3(NCAT/256, TOK/128), 256, GSMEMH>>>(
        xbh, WcatTh, dtbc, TOK, NCAT, INNER, bdt, nullptr);
    // 8) Wout -> WoutTh (f16)
    tr_f16<<<dim3(HIDDEN/32, INNER/32), dim3(32,8)>>>(Wout, WoutTh, INNER, HIDDEN);
    // 9) selective scan + gating -> f16 y
    scan_kernel<<<512, 128>>>(Alog, Dp);
    // 10) out = x + y @ W_out  (f16 mma + fp32 residual)
    gemm_f16k<2><<<dim3(HIDDEN/256, TOK/128), 256, GSMEMH>>>(
        yh, WoutTh, out, TOK, HIDDEN, INNER, nullptr, x);
}

// round 15
// speedup vs baseline: 1.1600x; 1.1600x over previous
#include <cuda_runtime.h>
#include <cuda_bf16.h>
#include <cstdint>
#include <math.h>

#define HIDDEN 1024
#define INNER  2048
#define STATE  16
#define BATCH  4
#define SEQ    2048
#define TOK    (BATCH*SEQ)   // 8192
#define NCAT   2304          // 2048 dt | 16 B | 16 C | 224 pad (9 tiles of 256)

// ---------------- scratch (static device globals) ---------------------------
__device__ __nv_bfloat16 g_xnh[TOK*HIDDEN];      // ln output (bf16, GEMM1 A)
__device__ float g_xz[TOK*2*INNER];              // GEMM1 out [xb_raw | z] fp32
__device__ float g_xb[TOK*INNER];                // conv+silu fp32 (scan)
__device__ __nv_bfloat16 g_xbh[TOK*INNER];       // conv+silu bf16 (GEMM2 A)
__device__ float g_dtbc[TOK*NCAT];               // [softplus(dt) | B | C | pad]
__device__ __nv_bfloat16 g_yh[TOK*INNER];        // gated SSM output (bf16, GEMM3 A)
__device__ __nv_bfloat16 g_WinTh [2*INNER*HIDDEN];
__device__ __nv_bfloat16 g_WcatTh[NCAT*INNER];
__device__ __nv_bfloat16 g_WoutTh[HIDDEN*INNER];

// ============================== helpers =====================================
__device__ __forceinline__ void cp16(uint32_t s, const void* g) {
    asm volatile("cp.async.cg.shared.global [%0], [%1], 16;" :: "r"(s), "l"(g));
}
__device__ __forceinline__ void cp_commit() {
    asm volatile("cp.async.commit_group;" ::: "memory");
}
template<int N> __device__ __forceinline__ void cp_wait() {
    asm volatile("cp.async.wait_group %0;" :: "n"(N) : "memory");
}
__device__ __forceinline__ void mma_bf16(float* d, const uint32_t* a, const uint32_t* b) {
    asm volatile("mma.sync.aligned.m16n8k16.row.col.f32.bf16.bf16.f32 "
                 "{%0,%1,%2,%3},{%4,%5,%6,%7},{%8,%9},{%0,%1,%2,%3};"
                 : "+f"(d[0]), "+f"(d[1]), "+f"(d[2]), "+f"(d[3])
                 : "r"(a[0]), "r"(a[1]), "r"(a[2]), "r"(a[3]), "r"(b[0]), "r"(b[1]));
}
__device__ __forceinline__ void ldmx4(uint32_t* r, uint32_t addr) {
    asm volatile("ldmatrix.sync.aligned.m8n8.x4.shared.b16 {%0,%1,%2,%3}, [%4];"
                 : "=r"(r[0]), "=r"(r[1]), "=r"(r[2]), "=r"(r[3]) : "r"(addr));
}
__device__ __forceinline__ float softplus_f(float v) {
    return fmaxf(v, 0.f) + __logf(1.f + __expf(-fabsf(v)));
}

// ====================== bf16 mma.sync GEMM (512 thr, 64x32 warp tiles) ======
// C[M,N] = A[M,K] @ Bt[N,K]^T, bf16 in, fp32 acc/out.
// BM=128, BN=256, BK=32, 512 threads (16 warps: 2m x 8n, 64x32 warp tiles),
// 4-stage cp.async pipeline. Rows padded to 80 B -> LDSM conflict-free.
// EPI: 0 plain, 1 mixed softplus(dt)|raw(bc), 2 +residual
#define PADH_B 80
#define AH_STAGE_B (128*PADH_B)               // 10240
#define BH_STAGE_B (256*PADH_B)               // 20480
#define GSMEMH (4*(AH_STAGE_B + BH_STAGE_B))  // 122880

template<int EPI>
__global__ __launch_bounds__(512) void gemm_bf16k(
    const __nv_bfloat16* __restrict__ A, const __nv_bfloat16* __restrict__ Bt,
    float* __restrict__ C, int M, int N, int K,
    const float* __restrict__ bias, const float* __restrict__ resid)
{
    extern __shared__ char smemc[];
    char* Abase = smemc;
    char* Bbase = smemc + 4*AH_STAGE_B;

    int tid = threadIdx.x, lane = tid & 31, wid = tid >> 5;
    int wm = wid >> 3, wn = wid & 7;          // 2 x 8 warp grid, 64x32 tiles
    int m0 = blockIdx.y * 128, n0 = blockIdx.x * 256;

    uint32_t uA = (uint32_t)__cvta_generic_to_shared(Abase);
    uint32_t uB = (uint32_t)__cvta_generic_to_shared(Bbase);

    const __nv_bfloat16* Agm = A  + (size_t)m0 * K;
    const __nv_bfloat16* Bgm = Bt + (size_t)n0 * K;

    int ns = K >> 5;                          // BK = 32

    auto load_stage = [&](int s) {
        int buf = s & 3;
        const __nv_bfloat16* Ak = Agm + s * 32;
        const __nv_bfloat16* Bk = Bgm + s * 32;
        uint32_t ab = uA + buf * AH_STAGE_B;
        uint32_t bb = uB + buf * BH_STAGE_B;
        {                                      // A: 512 x 16B
            int row = tid >> 2, c4 = tid & 3;
            cp16(ab + (uint32_t)(row*PADH_B + c4*16), Ak + (size_t)row * K + c4*8);
        }
        #pragma unroll
        for (int i = 0; i < 2; i++) {          // B: 1024 x 16B
            int e = tid + i * 512;
            int row = e >> 2, c4 = e & 3;
            cp16(bb + (uint32_t)(row*PADH_B + c4*16), Bk + (size_t)row * K + c4*8);
        }
        cp_commit();
    };

    load_stage(0); load_stage(1); load_stage(2);

    float acc[4][4][4] = {};

    // ldmatrix lane-offset maps (bytes)
    uint32_t aOff = (uint32_t)(((lane & 7) + ((lane >> 3) & 1) * 8) * PADH_B
                               + (lane >> 4) * 16);
    uint32_t bOff = (uint32_t)(((lane & 7) + (lane >> 4) * 8) * PADH_B
                               + ((lane >> 3) & 1) * 16);
    uint32_t aWarp = uA + (uint32_t)(wm*64*PADH_B) + aOff;
    uint32_t bWarp = uB + (uint32_t)(wn*32*PADH_B) + bOff;

    for (int s = 0; s < ns; s++) {
        cp_wait<2>();
        __syncthreads();
        if (s + 3 < ns) load_stage(s + 3);

        int buf = s & 3;
        uint32_t aStage = aWarp + buf * AH_STAGE_B;
        uint32_t bStage = bWarp + buf * BH_STAGE_B;
        #pragma unroll
        for (int ks = 0; ks < 2; ks++) {      // two k16 slices
            uint32_t af[4][4], bf[2][4];
            #pragma unroll
            for (int am = 0; am < 4; am++)
                ldmx4(af[am], aStage + (uint32_t)(am*16*PADH_B + ks*32));
            #pragma unroll
            for (int bp = 0; bp < 2; bp++)
                ldmx4(bf[bp], bStage + (uint32_t)(bp*16*PADH_B + ks*32));
            #pragma unroll
            for (int am = 0; am < 4; am++)
                #pragma unroll
                for (int bn = 0; bn < 4; bn++)
                    mma_bf16(acc[am][bn], af[am], &bf[bn >> 1][(bn & 1) * 2]);
        }
    }

    int r = lane >> 2, c = lane & 3;
    #pragma unroll
    for (int am = 0; am < 4; am++) {
        int row0 = m0 + wm*64 + am*16 + r;
        #pragma unroll
        for (int bn = 0; bn < 4; bn++) {
            int col = n0 + wn*32 + bn*8 + 2*c;
            #pragma unroll
            for (int h = 0; h < 2; h++) {
                int row = row0 + h*8;
                float v0 = acc[am][bn][h*2 + 0];
                float v1 = acc[am][bn][h*2 + 1];
                if (EPI == 1) {
                    if (col < 2048) {
                        v0 = softplus_f(v0 + bias[col]);
                        v1 = softplus_f(v1 + bias[col + 1]);
                    }
                } else if (EPI == 2) {
                    const float* rp = resid + (size_t)row * N + col;
                    v0 += rp[0]; v1 += rp[1];
                }
                *(float2*)(C + (size_t)row * N + col) = make_float2(v0, v1);
            }
        }
    }
}

// ------------------------------- weight prep --------------------------------
__global__ __launch_bounds__(256) void tr_bf16(
    const float* __restrict__ in, __nv_bfloat16* __restrict__ out, int K, int N)
{   // in [K,N] fp32 -> out [N,K] bf16
    __shared__ float tile[32][33];
    int tx = threadIdx.x, ty = threadIdx.y;
    int x = blockIdx.x * 32 + tx;
    int y = blockIdx.y * 32 + ty;
    #pragma unroll
    for (int j = 0; j < 32; j += 8)
        tile[ty + j][tx] = in[(size_t)(y + j) * N + x];
    __syncthreads();
    int x2 = blockIdx.y * 32 + tx;
    int y2 = blockIdx.x * 32 + ty;
    #pragma unroll
    for (int j = 0; j < 32; j += 8)
        out[(size_t)(y2 + j) * K + x2] = __float2bfloat16(tile[tx][ty + j]);
}

__global__ __launch_bounds__(256) void wbc_kernel(
    const float* __restrict__ WB, const float* __restrict__ WC)
{   // rows 2048..2303 of g_WcatTh: W_B^T, W_C^T, zeros
    int idx = blockIdx.x * 256 + threadIdx.x;     // 256*2048
    int j = idx >> 11, k = idx & 2047;
    float v = (j < 16) ? WB[(size_t)k*STATE + j]
            : (j < 32) ? WC[(size_t)k*STATE + (j - 16)]
            : 0.f;
    g_WcatTh[(size_t)(2048 + j) * INNER + k] = __float2bfloat16(v);
}

// ---------------------------------------------------------------- LayerNorm
__global__ __launch_bounds__(256) void ln_kernel(
    const float* __restrict__ x, const float* __restrict__ g,
    const float* __restrict__ bt)
{
    int r = blockIdx.x, t = threadIdx.x;
    float4 v = *(const float4*)(x + (size_t)r*HIDDEN + t*4);
    float s  = v.x + v.y + v.z + v.w;
    float s2 = v.x*v.x + v.y*v.y + v.z*v.z + v.w*v.w;
    #pragma unroll
    for (int off = 16; off > 0; off >>= 1) {
        s  += __shfl_xor_sync(0xffffffffu, s,  off);
        s2 += __shfl_xor_sync(0xffffffffu, s2, off);
    }
    __shared__ float a1[8], a2[8];
    if ((t & 31) == 0) { a1[t >> 5] = s; a2[t >> 5] = s2; }
    __syncthreads();
    float ts = 0.f, ts2 = 0.f;
    #pragma unroll
    for (int i = 0; i < 8; i++) { ts += a1[i]; ts2 += a2[i]; }
    float mu   = ts * (1.f / HIDDEN);
    float var  = fmaf(ts2, 1.f / HIDDEN, -mu * mu);
    float rstd = rsqrtf(var + 1e-5f);
    float4 g4 = *(const float4*)(g  + t*4);
    float4 b4 = *(const float4*)(bt + t*4);
    float4 ov;
    ov.x = (v.x - mu) * rstd * g4.x + b4.x;
    ov.y = (v.y - mu) * rstd * g4.y + b4.y;
    ov.z = (v.z - mu) * rstd * g4.z + b4.z;
    ov.w = (v.w - mu) * rstd * g4.w + b4.w;
    union { __nv_bfloat162 h[2]; uint2 u; } pk;
    pk.h[0] = __floats2bfloat162_rn(ov.x, ov.y);
    pk.h[1] = __floats2bfloat162_rn(ov.z, ov.w);
    *(uint2*)(g_xnh + (size_t)r*HIDDEN + t*4) = pk.u;
}

// ----------------------------------------------- depthwise conv (k=3) + SiLU
__global__ __launch_bounds__(256) void conv_kernel(
    const float* __restrict__ cw, const float* __restrict__ cb)
{
    int idx = blockIdx.x * 256 + threadIdx.x;
    int d4 = idx & 511;
    int r  = idx >> 9;
    int l  = r & (SEQ - 1);
    const float* base = g_xz + (size_t)r*(2*INNER) + d4*4;
    float4 zero = make_float4(0.f, 0.f, 0.f, 0.f);
    float4 xm = (l > 0)       ? *(const float4*)(base - 2*INNER) : zero;
    float4 xc = *(const float4*)(base);
    float4 xp = (l < SEQ - 1) ? *(const float4*)(base + 2*INNER) : zero;
    const float4* cwp = (const float4*)(cw + d4*12);
    float4 t0 = cwp[0], t1 = cwp[1], t2 = cwp[2];
    float4 b4 = *(const float4*)(cb + d4*4);
    float o0 = t0.x*xm.x + t0.y*xc.x + t0.z*xp.x + b4.x;
    float o1 = t0.w*xm.y + t1.x*xc.y + t1.y*xp.y + b4.y;
    float o2 = t1.z*xm.z + t1.w*xc.z + t2.x*xp.z + b4.z;
    float o3 = t2.y*xm.w + t2.z*xc.w + t2.w*xp.w + b4.w;
    o0 *= __fdividef(1.f, 1.f + __expf(-o0));
    o1 *= __fdividef(1.f, 1.f + __expf(-o1));
    o2 *= __fdividef(1.f, 1.f + __expf(-o2));
    o3 *= __fdividef(1.f, 1.f + __expf(-o3));
    *(float4*)(g_xb + (size_t)r*INNER + d4*4) = make_float4(o0, o1, o2, o3);
    union { __nv_bfloat162 h[2]; uint2 u; } pk;
    pk.h[0] = __floats2bfloat162_rn(o0, o1);
    pk.h[1] = __floats2bfloat162_rn(o2, o3);
    *(uint2*)(g_xbh + (size_t)r*INNER + d4*4) = pk.u;
}

// ---------------------------- selective scan + gating -----------------------
__global__ __launch_bounds__(128) void scan_kernel(
    const float* __restrict__ A_log, const float* __restrict__ Dp)
{
    __shared__ float s_dt[2][16][16];
    __shared__ float s_x [2][16][16];
    __shared__ float s_z [2][16][16];
    __shared__ float s_bc[2][16][32];
    __shared__ float s_y [16][16];

    int tid = threadIdx.x;
    int b  = blockIdx.x >> 7;
    int d0 = (blockIdx.x & 127) * 16;
    int q  = tid & 7, dl = tid >> 3;
    int d  = d0 + dl;

    float a0 = -__expf(A_log[d*STATE + 2*q]);
    float a1 = -__expf(A_log[d*STATE + 2*q + 1]);
    float Dd = Dp[d];
    size_t tokbase = (size_t)b * SEQ;

    uint32_t u_dt = (uint32_t)__cvta_generic_to_shared(&s_dt[0][0][0]);
    uint32_t u_x  = (uint32_t)__cvta_generic_to_shared(&s_x [0][0][0]);
    uint32_t u_z  = (uint32_t)__cvta_generic_to_shared(&s_z [0][0][0]);
    uint32_t u_bc = (uint32_t)__cvta_generic_to_shared(&s_bc[0][0][0]);

    auto stage = [&](int s) {
        int l0 = s * 16, buf = s & 1;
        #pragma unroll
        for (int ii = tid; ii < 320; ii += 128) {
            if (ii < 192) {
                int arr = ii >> 6, e = ii & 63;
                int rowi = e >> 2, c4 = e & 3;
                size_t tok = tokbase + l0 + rowi;
                uint32_t doff = (uint32_t)((rowi*16 + c4*4) * 4) + buf*1024;
                if (arr == 0)
                    cp16(u_dt + doff, g_dtbc + tok*NCAT + d0 + c4*4);
                else if (arr == 1)
                    cp16(u_x + doff, g_xb + tok*INNER + d0 + c4*4);
                else
                    cp16(u_z + doff, g_xz + tok*(2*INNER) + INNER + d0 + c4*4);
            } else {
                int e = ii - 192;
                int rowi = e >> 3, c8 = e & 7;
                size_t tok = tokbase + l0 + rowi;
                cp16(u_bc + buf*2048 + (uint32_t)((rowi*32 + c8*4) * 4),
                     g_dtbc + tok*NCAT + 2048 + c8*4);
            }
        }
    };

    stage(0); cp_commit();

    float h0 = 0.f, h1 = 0.f;
    for (int s = 0; s < SEQ/16; s++) {
        if (s + 1 < SEQ/16) { stage(s + 1); cp_commit(); cp_wait<1>(); }
        else cp_wait<0>();
        __syncthreads();

        int buf = s & 1;
        #pragma unroll
        for (int i = 0; i < 16; i++) {
            float dtc = s_dt[buf][i][dl];
            float xc  = s_x [buf][i][dl];
            float2 Bv = *(const float2*)&s_bc[buf][i][2*q];
            float2 Cv = *(const float2*)&s_bc[buf][i][16 + 2*q];
            float e0 = __expf(dtc * a0);
            float e1 = __expf(dtc * a1);
            float dx = dtc * xc;
            h0 = fmaf(e0, h0, dx * Bv.x);
            h1 = fmaf(e1, h1, dx * Bv.y);
            float p = fmaf(h1, Cv.y, h0 * Cv.x);
            p += __shfl_xor_sync(0xffffffffu, p, 1);
            p += __shfl_xor_sync(0xffffffffu, p, 2);
            p += __shfl_xor_sync(0xffffffffu, p, 4);
            if (q == 0) {
                float zz  = s_z[buf][i][dl];
                float sil = zz * __fdividef(1.f, 1.f + __expf(-zz));
                s_y[i][dl] = fmaf(Dd, xc, p) * sil;
            }
        }
        __syncthreads();
        if (tid < 64) {
            int rowi = tid >> 2, c4 = tid & 3;
            float4 v = *(float4*)&s_y[rowi][c4*4];
            union { __nv_bfloat162 h[2]; uint2 u; } pk;
            pk.h[0] = __floats2bfloat162_rn(v.x, v.y);
            pk.h[1] = __floats2bfloat162_rn(v.z, v.w);
            *(uint2*)(g_yh + (tokbase + s*16 + rowi)*INNER + d0 + c4*4) = pk.u;
        }
    }
}

// ------------------------------------------------------------------- launch
extern "C" void kernel_launch(void* const* d_in, const int* in_sizes, int n_in,
                              void* d_out, int out_size)
{
    const float* x    = (const float*)d_in[0];
    const float* ns   = (const float*)d_in[1];
    const float* nb   = (const float*)d_in[2];
    const float* Win  = (const float*)d_in[3];
    const float* cw   = (const float*)d_in[4];
    const float* cb   = (const float*)d_in[5];
    const float* Wdt  = (const float*)d_in[6];
    const float* bdt  = (const float*)d_in[7];
    const float* Alog = (const float*)d_in[8];
    const float* Dp   = (const float*)d_in[9];
    const float* WB   = (const float*)d_in[10];
    const float* WC   = (const float*)d_in[11];
    const float* Wout = (const float*)d_in[12];
    float* out = (float*)d_out;

    void *p_xnh, *p_xz, *p_xbh, *p_dtbc, *p_yh, *p_winth, *p_wcatth, *p_woutth;
    cudaGetSymbolAddress(&p_xnh,  g_xnh);
    cudaGetSymbolAddress(&p_xz,   g_xz);
    cudaGetSymbolAddress(&p_xbh,  g_xbh);
    cudaGetSymbolAddress(&p_dtbc, g_dtbc);
    cudaGetSymbolAddress(&p_yh,   g_yh);
    cudaGetSymbolAddress(&p_winth,  g_WinTh);
    cudaGetSymbolAddress(&p_wcatth, g_WcatTh);
    cudaGetSymbolAddress(&p_woutth, g_WoutTh);
    __nv_bfloat16* xnh   = (__nv_bfloat16*)p_xnh;
    float*         xz    = (float*)p_xz;
    __nv_bfloat16* xbh   = (__nv_bfloat16*)p_xbh;
    float*         dtbc  = (float*)p_dtbc;
    __nv_bfloat16* yh    = (__nv_bfloat16*)p_yh;
    __nv_bfloat16* WinTh  = (__nv_bfloat16*)p_winth;
    __nv_bfloat16* WcatTh = (__nv_bfloat16*)p_wcatth;
    __nv_bfloat16* WoutTh = (__nv_bfloat16*)p_woutth;

    cudaFuncSetAttribute(gemm_bf16k<0>, cudaFuncAttributeMaxDynamicSharedMemorySize, GSMEMH);
    cudaFuncSetAttribute(gemm_bf16k<1>, cudaFuncAttributeMaxDynamicSharedMemorySize, GSMEMH);
    cudaFuncSetAttribute(gemm_bf16k<2>, cudaFuncAttributeMaxDynamicSharedMemorySize, GSMEMH);

    // launch order: gemm_bf16k<0> is the 4th launch (ncu target)
    // 1) Win -> WinTh (bf16)
    tr_bf16<<<dim3(2*INNER/32, HIDDEN/32), dim3(32,8)>>>(Win, WinTh, HIDDEN, 2*INNER);
    // 2) LayerNorm -> bf16
    ln_kernel<<<TOK, 256>>>(x, ns, nb);
    // 3) WB/WC rows of WcatTh
    wbc_kernel<<<(256*2048)/256, 256>>>(WB, WC);
    // 4) xz = xn @ W_in   (bf16 mma)  <-- profiled
    gemm_bf16k<0><<<dim3(2*INNER/256, TOK/128), 512, GSMEMH>>>(
        xnh, WinTh, xz, TOK, 2*INNER, HIDDEN, nullptr, nullptr);
    // 5) Wdt -> WcatTh rows 0..2047
    tr_bf16<<<dim3(INNER/32, INNER/32), dim3(32,8)>>>(Wdt, WcatTh, INNER, INNER);
    // 6) conv + SiLU (fp32 + bf16 outputs)
    conv_kernel<<<(TOK*INNER/4)/256, 256>>>(cw, cb);
    // 7) [dt | B | C] = xb @ Wcat  (bf16 mma, softplus on dt cols)
    gemm_bf16k<1><<<dim3(NCAT/256, TOK/128), 512, GSMEMH>>>(
        xbh, WcatTh, dtbc, TOK, NCAT, INNER, bdt, nullptr);
    // 8) Wout -> WoutTh (bf16)
    tr_bf16<<<dim3(HIDDEN/32, INNER/32), dim3(32,8)>>>(Wout, WoutTh, INNER, HIDDEN);
    // 9) selective scan + gating -> bf16 y
    scan_kernel<<<512, 128>>>(Alog, Dp);
    // 10) out = x + y @ W_out  (bf16 mma + fp32 residual)
    gemm_bf16k<2><<<dim3(HIDDEN/256, TOK/128), 512, GSMEMH>>>(
        yh, WoutTh, out, TOK, HIDDEN, INNER, nullptr, x);
}

// round 17
// speedup vs baseline: 1.3886x; 1.1970x over previous
#include <cuda_runtime.h>
#include <cuda_bf16.h>
#include <cstdint>
#include <math.h>

#define HIDDEN 1024
#define INNER  2048
#define STATE  16
#define BATCH  4
#define SEQ    2048
#define TOK    (BATCH*SEQ)   // 8192
#define NCAT   2304          // 2048 dt | 16 B | 16 C | 224 pad (9 tiles of 256)

// ---------------- scratch (static device globals) ---------------------------
__device__ __nv_bfloat16 g_xnh[TOK*HIDDEN];      // ln output (bf16, GEMM1 A)
__device__ float g_xz[TOK*2*INNER];              // GEMM1 out [xb_raw | z] fp32
__device__ float g_xb[TOK*INNER];                // conv+silu fp32 (scan)
__device__ __nv_bfloat16 g_xbh[TOK*INNER];       // conv+silu bf16 (GEMM2 A)
__device__ float g_dtbc[TOK*NCAT];               // [softplus(dt) | B | C | pad]
__device__ __nv_bfloat16 g_yh[TOK*INNER];        // gated SSM output (bf16, GEMM3 A)
__device__ __nv_bfloat16 g_WinTh [2*INNER*HIDDEN];
__device__ __nv_bfloat16 g_WcatTh[NCAT*INNER];
__device__ __nv_bfloat16 g_WoutTh[HIDDEN*INNER];

// ============================== helpers =====================================
__device__ __forceinline__ void cp16(uint32_t s, const void* g) {
    asm volatile("cp.async.cg.shared.global [%0], [%1], 16;" :: "r"(s), "l"(g));
}
__device__ __forceinline__ void cp_commit() {
    asm volatile("cp.async.commit_group;" ::: "memory");
}
template<int N> __device__ __forceinline__ void cp_wait() {
    asm volatile("cp.async.wait_group %0;" :: "n"(N) : "memory");
}
__device__ __forceinline__ void mma_bf16(float* d, const uint32_t* a, const uint32_t* b) {
    asm volatile("mma.sync.aligned.m16n8k16.row.col.f32.bf16.bf16.f32 "
                 "{%0,%1,%2,%3},{%4,%5,%6,%7},{%8,%9},{%0,%1,%2,%3};"
                 : "+f"(d[0]), "+f"(d[1]), "+f"(d[2]), "+f"(d[3])
                 : "r"(a[0]), "r"(a[1]), "r"(a[2]), "r"(a[3]), "r"(b[0]), "r"(b[1]));
}
__device__ __forceinline__ void ldmx4(uint32_t* r, uint32_t addr) {
    asm volatile("ldmatrix.sync.aligned.m8n8.x4.shared.b16 {%0,%1,%2,%3}, [%4];"
                 : "=r"(r[0]), "=r"(r[1]), "=r"(r[2]), "=r"(r[3]) : "r"(addr));
}
__device__ __forceinline__ float softplus_f(float v) {
    return fmaxf(v, 0.f) + __logf(1.f + __expf(-fabsf(v)));
}

// ====================== bf16 mma.sync GEMM (512 thr, 64x32 warp tiles) ======
// C[M,N] = A[M,K] @ Bt[N,K]^T, bf16 in, fp32 acc/out.
// BM=128, BN=256, BK=32, 512 threads (16 warps: 2m x 8n, 64x32 warp tiles),
// 4-stage cp.async pipeline. Rows padded to 80 B -> LDSM conflict-free.
// EPI: 0 plain, 1 mixed softplus(dt)|raw(bc), 2 +residual
#define PADH_B 80
#define AH_STAGE_B (128*PADH_B)               // 10240
#define BH_STAGE_B (256*PADH_B)               // 20480
#define GSMEMH (4*(AH_STAGE_B + BH_STAGE_B))  // 122880

template<int EPI>
__global__ __launch_bounds__(512) void gemm_bf16k(
    const __nv_bfloat16* __restrict__ A, const __nv_bfloat16* __restrict__ Bt,
    float* __restrict__ C, int M, int N, int K,
    const float* __restrict__ bias, const float* __restrict__ resid)
{
    extern __shared__ char smemc[];
    char* Abase = smemc;
    char* Bbase = smemc + 4*AH_STAGE_B;

    int tid = threadIdx.x, lane = tid & 31, wid = tid >> 5;
    int wm = wid >> 3, wn = wid & 7;          // 2 x 8 warp grid, 64x32 tiles
    int m0 = blockIdx.y * 128, n0 = blockIdx.x * 256;

    uint32_t uA = (uint32_t)__cvta_generic_to_shared(Abase);
    uint32_t uB = (uint32_t)__cvta_generic_to_shared(Bbase);

    const __nv_bfloat16* Agm = A  + (size_t)m0 * K;
    const __nv_bfloat16* Bgm = Bt + (size_t)n0 * K;

    int ns = K >> 5;                          // BK = 32

    auto load_stage = [&](int s) {
        int buf = s & 3;
        const __nv_bfloat16* Ak = Agm + s * 32;
        const __nv_bfloat16* Bk = Bgm + s * 32;
        uint32_t ab = uA + buf * AH_STAGE_B;
        uint32_t bb = uB + buf * BH_STAGE_B;
        {                                      // A: 512 x 16B
            int row = tid >> 2, c4 = tid & 3;
            cp16(ab + (uint32_t)(row*PADH_B + c4*16), Ak + (size_t)row * K + c4*8);
        }
        #pragma unroll
        for (int i = 0; i < 2; i++) {          // B: 1024 x 16B
            int e = tid + i * 512;
            int row = e >> 2, c4 = e & 3;
            cp16(bb + (uint32_t)(row*PADH_B + c4*16), Bk + (size_t)row * K + c4*8);
        }
        cp_commit();
    };

    load_stage(0); load_stage(1); load_stage(2);

    float acc[4][4][4] = {};

    // ldmatrix lane-offset maps (bytes)
    uint32_t aOff = (uint32_t)(((lane & 7) + ((lane >> 3) & 1) * 8) * PADH_B
                               + (lane >> 4) * 16);
    uint32_t bOff = (uint32_t)(((lane & 7) + (lane >> 4) * 8) * PADH_B
                               + ((lane >> 3) & 1) * 16);
    uint32_t aWarp = uA + (uint32_t)(wm*64*PADH_B) + aOff;
    uint32_t bWarp = uB + (uint32_t)(wn*32*PADH_B) + bOff;

    for (int s = 0; s < ns; s++) {
        cp_wait<2>();
        __syncthreads();
        if (s + 3 < ns) load_stage(s + 3);

        int buf = s & 3;
        uint32_t aStage = aWarp + buf * AH_STAGE_B;
        uint32_t bStage = bWarp + buf * BH_STAGE_B;
        #pragma unroll
        for (int ks = 0; ks < 2; ks++) {      // two k16 slices
            uint32_t af[4][4], bf[2][4];
            #pragma unroll
            for (int am = 0; am < 4; am++)
                ldmx4(af[am], aStage + (uint32_t)(am*16*PADH_B + ks*32));
            #pragma unroll
            for (int bp = 0; bp < 2; bp++)
                ldmx4(bf[bp], bStage + (uint32_t)(bp*16*PADH_B + ks*32));
            #pragma unroll
            for (int am = 0; am < 4; am++)
                #pragma unroll
                for (int bn = 0; bn < 4; bn++)
                    mma_bf16(acc[am][bn], af[am], &bf[bn >> 1][(bn & 1) * 2]);
        }
    }

    int r = lane >> 2, c = lane & 3;
    #pragma unroll
    for (int am = 0; am < 4; am++) {
        int row0 = m0 + wm*64 + am*16 + r;
        #pragma unroll
        for (int bn = 0; bn < 4; bn++) {
            int col = n0 + wn*32 + bn*8 + 2*c;
            #pragma unroll
            for (int h = 0; h < 2; h++) {
                int row = row0 + h*8;
                float v0 = acc[am][bn][h*2 + 0];
                float v1 = acc[am][bn][h*2 + 1];
                if (EPI == 1) {
                    if (col < 2048) {
                        v0 = softplus_f(v0 + bias[col]);
                        v1 = softplus_f(v1 + bias[col + 1]);
                    }
                } else if (EPI == 2) {
                    const float* rp = resid + (size_t)row * N + col;
                    v0 += rp[0]; v1 += rp[1];
                }
                *(float2*)(C + (size_t)row * N + col) = make_float2(v0, v1);
            }
        }
    }
}

// ------------------------------- weight prep --------------------------------
__global__ __launch_bounds__(256) void tr_bf16(
    const float* __restrict__ in, __nv_bfloat16* __restrict__ out, int K, int N)
{   // in [K,N] fp32 -> out [N,K] bf16
    __shared__ float tile[32][33];
    int tx = threadIdx.x, ty = threadIdx.y;
    int x = blockIdx.x * 32 + tx;
    int y = blockIdx.y * 32 + ty;
    #pragma unroll
    for (int j = 0; j < 32; j += 8)
        tile[ty + j][tx] = in[(size_t)(y + j) * N + x];
    __syncthreads();
    int x2 = blockIdx.y * 32 + tx;
    int y2 = blockIdx.x * 32 + ty;
    #pragma unroll
    for (int j = 0; j < 32; j += 8)
        out[(size_t)(y2 + j) * K + x2] = __float2bfloat16(tile[tx][ty + j]);
}

__global__ __launch_bounds__(256) void wbc_kernel(
    const float* __restrict__ WB, const float* __restrict__ WC)
{   // rows 2048..2303 of g_WcatTh: W_B^T, W_C^T, zeros
    int idx = blockIdx.x * 256 + threadIdx.x;     // 256*2048
    int j = idx >> 11, k = idx & 2047;
    float v = (j < 16) ? WB[(size_t)k*STATE + j]
            : (j < 32) ? WC[(size_t)k*STATE + (j - 16)]
            : 0.f;
    g_WcatTh[(size_t)(2048 + j) * INNER + k] = __float2bfloat16(v);
}

// ---------------------------------------------------------------- LayerNorm
__global__ __launch_bounds__(256) void ln_kernel(
    const float* __restrict__ x, const float* __restrict__ g,
    const float* __restrict__ bt)
{
    int r = blockIdx.x, t = threadIdx.x;
    float4 v = *(const float4*)(x + (size_t)r*HIDDEN + t*4);
    float s  = v.x + v.y + v.z + v.w;
    float s2 = v.x*v.x + v.y*v.y + v.z*v.z + v.w*v.w;
    #pragma unroll
    for (int off = 16; off > 0; off >>= 1) {
        s  += __shfl_xor_sync(0xffffffffu, s,  off);
        s2 += __shfl_xor_sync(0xffffffffu, s2, off);
    }
    __shared__ float a1[8], a2[8];
    if ((t & 31) == 0) { a1[t >> 5] = s; a2[t >> 5] = s2; }
    __syncthreads();
    float ts = 0.f, ts2 = 0.f;
    #pragma unroll
    for (int i = 0; i < 8; i++) { ts += a1[i]; ts2 += a2[i]; }
    float mu   = ts * (1.f / HIDDEN);
    float var  = fmaf(ts2, 1.f / HIDDEN, -mu * mu);
    float rstd = rsqrtf(var + 1e-5f);
    float4 g4 = *(const float4*)(g  + t*4);
    float4 b4 = *(const float4*)(bt + t*4);
    float4 ov;
    ov.x = (v.x - mu) * rstd * g4.x + b4.x;
    ov.y = (v.y - mu) * rstd * g4.y + b4.y;
    ov.z = (v.z - mu) * rstd * g4.z + b4.z;
    ov.w = (v.w - mu) * rstd * g4.w + b4.w;
    union { __nv_bfloat162 h[2]; uint2 u; } pk;
    pk.h[0] = __floats2bfloat162_rn(ov.x, ov.y);
    pk.h[1] = __floats2bfloat162_rn(ov.z, ov.w);
    *(uint2*)(g_xnh + (size_t)r*HIDDEN + t*4) = pk.u;
}

// ----------------------------------------------- depthwise conv (k=3) + SiLU
__global__ __launch_bounds__(256) void conv_kernel(
    const float* __restrict__ cw, const float* __restrict__ cb)
{
    int idx = blockIdx.x * 256 + threadIdx.x;
    int d4 = idx & 511;
    int r  = idx >> 9;
    int l  = r & (SEQ - 1);
    const float* base = g_xz + (size_t)r*(2*INNER) + d4*4;
    float4 zero = make_float4(0.f, 0.f, 0.f, 0.f);
    float4 xm = (l > 0)       ? *(const float4*)(base - 2*INNER) : zero;
    float4 xc = *(const float4*)(base);
    float4 xp = (l < SEQ - 1) ? *(const float4*)(base + 2*INNER) : zero;
    const float4* cwp = (const float4*)(cw + d4*12);
    float4 t0 = cwp[0], t1 = cwp[1], t2 = cwp[2];
    float4 b4 = *(const float4*)(cb + d4*4);
    float o0 = t0.x*xm.x + t0.y*xc.x + t0.z*xp.x + b4.x;
    float o1 = t0.w*xm.y + t1.x*xc.y + t1.y*xp.y + b4.y;
    float o2 = t1.z*xm.z + t1.w*xc.z + t2.x*xp.z + b4.z;
    float o3 = t2.y*xm.w + t2.z*xc.w + t2.w*xp.w + b4.w;
    o0 *= __fdividef(1.f, 1.f + __expf(-o0));
    o1 *= __fdividef(1.f, 1.f + __expf(-o1));
    o2 *= __fdividef(1.f, 1.f + __expf(-o2));
    o3 *= __fdividef(1.f, 1.f + __expf(-o3));
    *(float4*)(g_xb + (size_t)r*INNER + d4*4) = make_float4(o0, o1, o2, o3);
    union { __nv_bfloat162 h[2]; uint2 u; } pk;
    pk.h[0] = __floats2bfloat162_rn(o0, o1);
    pk.h[1] = __floats2bfloat162_rn(o2, o3);
    *(uint2*)(g_xbh + (size_t)r*INNER + d4*4) = pk.u;
}

// ---------------------------- selective scan + gating -----------------------
// 128 thr: 16 d x 8 state-pairs. Inner loop = recurrence only (STS partials);
// 8-way N-reduce + D*x + SiLU gating done in a batched smem phase per stage.
__global__ __launch_bounds__(128) void scan_kernel(
    const float* __restrict__ A_log, const float* __restrict__ Dp)
{
    __shared__ float s_dt[2][16][16];
    __shared__ float s_x [2][16][16];
    __shared__ float s_z [2][16][16];
    __shared__ float s_bc[2][16][32];
    __shared__ float s_p [16][128];     // [step][dl*8+q] partial products
    __shared__ float s_D [16];

    int tid = threadIdx.x;
    int b  = blockIdx.x >> 7;
    int d0 = (blockIdx.x & 127) * 16;
    int q  = tid & 7, dl = tid >> 3;
    int d  = d0 + dl;

    float a0 = -__expf(A_log[d*STATE + 2*q]);
    float a1 = -__expf(A_log[d*STATE + 2*q + 1]);
    if (tid < 16) s_D[tid] = Dp[d0 + tid];
    size_t tokbase = (size_t)b * SEQ;

    uint32_t u_dt = (uint32_t)__cvta_generic_to_shared(&s_dt[0][0][0]);
    uint32_t u_x  = (uint32_t)__cvta_generic_to_shared(&s_x [0][0][0]);
    uint32_t u_z  = (uint32_t)__cvta_generic_to_shared(&s_z [0][0][0]);
    uint32_t u_bc = (uint32_t)__cvta_generic_to_shared(&s_bc[0][0][0]);

    auto stage = [&](int s) {
        int l0 = s * 16, buf = s & 1;
        #pragma unroll
        for (int ii = tid; ii < 320; ii += 128) {
            if (ii < 192) {
                int arr = ii >> 6, e = ii & 63;
                int rowi = e >> 2, c4 = e & 3;
                size_t tok = tokbase + l0 + rowi;
                uint32_t doff = (uint32_t)((rowi*16 + c4*4) * 4) + buf*1024;
                if (arr == 0)
                    cp16(u_dt + doff, g_dtbc + tok*NCAT + d0 + c4*4);
                else if (arr == 1)
                    cp16(u_x + doff, g_xb + tok*INNER + d0 + c4*4);
                else
                    cp16(u_z + doff, g_xz + tok*(2*INNER) + INNER + d0 + c4*4);
            } else {
                int e = ii - 192;
                int rowi = e >> 3, c8 = e & 7;
                size_t tok = tokbase + l0 + rowi;
                cp16(u_bc + buf*2048 + (uint32_t)((rowi*32 + c8*4) * 4),
                     g_dtbc + tok*NCAT + 2048 + c8*4);
            }
        }
    };

    stage(0); cp_commit();

    float h0 = 0.f, h1 = 0.f;
    for (int s = 0; s < SEQ/16; s++) {
        if (s + 1 < SEQ/16) { stage(s + 1); cp_commit(); cp_wait<1>(); }
        else cp_wait<0>();
        __syncthreads();   // stage data ready; also protects s_p from prev reduce

        int buf = s & 1;
        // ---- recurrence only: no cross-lane ops ----
        #pragma unroll
        for (int i = 0; i < 16; i++) {
            float dtc = s_dt[buf][i][dl];
            float xc  = s_x [buf][i][dl];
            float2 Bv = *(const float2*)&s_bc[buf][i][2*q];
            float2 Cv = *(const float2*)&s_bc[buf][i][16 + 2*q];
            float e0 = __expf(dtc * a0);
            float e1 = __expf(dtc * a1);
            float dx = dtc * xc;
            h0 = fmaf(e0, h0, dx * Bv.x);
            h1 = fmaf(e1, h1, dx * Bv.y);
            s_p[i][tid] = fmaf(h1, Cv.y, h0 * Cv.x);   // tid == dl*8+q
        }
        __syncthreads();

        // ---- batched reduce + gate + store: 256 (step,d) pairs, 2/thread ----
        #pragma unroll
        for (int t = 0; t < 2; t++) {
            int idx = tid + t * 128;
            int i = idx >> 4, dlr = idx & 15;
            const float* pp = &s_p[i][dlr * 8];
            float4 v0 = *(const float4*)pp;
            float4 v1 = *(const float4*)(pp + 4);
            float sum = ((v0.x + v0.y) + (v0.z + v0.w))
                      + ((v1.x + v1.y) + (v1.z + v1.w));
            float xc = s_x[buf][i][dlr];
            float zz = s_z[buf][i][dlr];
            float sil = zz * __fdividef(1.f, 1.f + __expf(-zz));
            float y = fmaf(s_D[dlr], xc, sum) * sil;
            g_yh[(tokbase + s*16 + i) * INNER + d0 + dlr] = __float2bfloat16(y);
        }
    }
}

// ------------------------------------------------------------------- launch
extern "C" void kernel_launch(void* const* d_in, const int* in_sizes, int n_in,
                              void* d_out, int out_size)
{
    const float* x    = (const float*)d_in[0];
    const float* ns   = (const float*)d_in[1];
    const float* nb   = (const float*)d_in[2];
    const float* Win  = (const float*)d_in[3];
    const float* cw   = (const float*)d_in[4];
    const float* cb   = (const float*)d_in[5];
    const float* Wdt  = (const float*)d_in[6];
    const float* bdt  = (const float*)d_in[7];
    const float* Alog = (const float*)d_in[8];
    const float* Dp   = (const float*)d_in[9];
    const float* WB   = (const float*)d_in[10];
    const float* WC   = (const float*)d_in[11];
    const float* Wout = (const float*)d_in[12];
    float* out = (float*)d_out;

    void *p_xnh, *p_xz, *p_xbh, *p_dtbc, *p_yh, *p_winth, *p_wcatth, *p_woutth;
    cudaGetSymbolAddress(&p_xnh,  g_xnh);
    cudaGetSymbolAddress(&p_xz,   g_xz);
    cudaGetSymbolAddress(&p_xbh,  g_xbh);
    cudaGetSymbolAddress(&p_dtbc, g_dtbc);
    cudaGetSymbolAddress(&p_yh,   g_yh);
    cudaGetSymbolAddress(&p_winth,  g_WinTh);
    cudaGetSymbolAddress(&p_wcatth, g_WcatTh);
    cudaGetSymbolAddress(&p_woutth, g_WoutTh);
    __nv_bfloat16* xnh   = (__nv_bfloat16*)p_xnh;
    float*         xz    = (float*)p_xz;
    __nv_bfloat16* xbh   = (__nv_bfloat16*)p_xbh;
    float*         dtbc  = (float*)p_dtbc;
    __nv_bfloat16* yh    = (__nv_bfloat16*)p_yh;
    __nv_bfloat16* WinTh  = (__nv_bfloat16*)p_winth;
    __nv_bfloat16* WcatTh = (__nv_bfloat16*)p_wcatth;
    __nv_bfloat16* WoutTh = (__nv_bfloat16*)p_woutth;

    cudaFuncSetAttribute(gemm_bf16k<0>, cudaFuncAttributeMaxDynamicSharedMemorySize, GSMEMH);
    cudaFuncSetAttribute(gemm_bf16k<1>, cudaFuncAttributeMaxDynamicSharedMemorySize, GSMEMH);
    cudaFuncSetAttribute(gemm_bf16k<2>, cudaFuncAttributeMaxDynamicSharedMemorySize, GSMEMH);

    // launch order: gemm_bf16k<0> is the 4th launch (ncu target)
    // 1) Win -> WinTh (bf16)
    tr_bf16<<<dim3(2*INNER/32, HIDDEN/32), dim3(32,8)>>>(Win, WinTh, HIDDEN, 2*INNER);
    // 2) LayerNorm -> bf16
    ln_kernel<<<TOK, 256>>>(x, ns, nb);
    // 3) WB/WC rows of WcatTh
    wbc_kernel<<<(256*2048)/256, 256>>>(WB, WC);
    // 4) xz = xn @ W_in   (bf16 mma)  <-- profiled
    gemm_bf16k<0><<<dim3(2*INNER/256, TOK/128), 512, GSMEMH>>>(
        xnh, WinTh, xz, TOK, 2*INNER, HIDDEN, nullptr, nullptr);
    // 5) Wdt -> WcatTh rows 0..2047
    tr_bf16<<<dim3(INNER/32, INNER/32), dim3(32,8)>>>(Wdt, WcatTh, INNER, INNER);
    // 6) conv + SiLU (fp32 + bf16 outputs)
    conv_kernel<<<(TOK*INNER/4)/256, 256>>>(cw, cb);
    // 7) [dt | B | C] = xb @ Wcat  (bf16 mma, softplus on dt cols)
    gemm_bf16k<1><<<dim3(NCAT/256, TOK/128), 512, GSMEMH>>>(
        xbh, WcatTh, dtbc, TOK, NCAT, INNER, bdt, nullptr);
    // 8) Wout -> WoutTh (bf16)
    tr_bf16<<<dim3(HIDDEN/32, INNER/32), dim3(32,8)>>>(Wout, WoutTh, INNER, HIDDEN);
    // 9) selective scan + gating -> bf16 y
    scan_kernel<<<512, 128>>>(Alog, Dp);
    // 10) out = x + y @ W_out  (bf16 mma + fp32 residual)
    gemm_bf16k<2><<<dim3(HIDDEN/256, TOK/128), 512, GSMEMH>>>(
        yh, WoutTh, out, TOK, HIDDEN, INNER, nullptr, x);
}